// round 6
// baseline (speedup 1.0000x reference)
#include <cuda_runtime.h>
#include <cuda_bf16.h>
#include <cstdint>
#include <cstddef>

#define SEQ   2048
#define EMB   1024
#define HID   1024
#define VOC   50257
#define GATES 4096
#define NCTA  128

// ---------------- device scratch (static) ----------------
__device__ __nv_bfloat16 g_x[SEQ * EMB];
__device__ __nv_bfloat16 g_Wih[GATES * EMB];
__device__ __nv_bfloat16 g_Wout[(size_t)VOC * HID];
__device__ __nv_bfloat16 g_hs[SEQ * HID];
__device__ float         g_xgates[SEQ * GATES];
__device__ float         g_h[2][HID];
__device__ float         g_bias4[GATES];
__device__ unsigned      g_flag[NCTA];

// ---------------- prep kernels ----------------
__global__ void k_init() { if (threadIdx.x < NCTA) g_flag[threadIdx.x] = 0u; }

__global__ void k_bias(const float* __restrict__ bih, const float* __restrict__ bhh) {
    int i = blockIdx.x * blockDim.x + threadIdx.x;
    if (i < GATES) g_bias4[i] = bih[i] + bhh[i];
}

__global__ void k_conv(const float* __restrict__ src, __nv_bfloat16* __restrict__ dst, size_t n4) {
    size_t i = (size_t)blockIdx.x * blockDim.x + threadIdx.x;
    if (i < n4) {
        float4 v = ((const float4*)src)[i];
        __nv_bfloat162* d2 = (__nv_bfloat162*)dst;
        d2[2*i]   = __floats2bfloat162_rn(v.x, v.y);
        d2[2*i+1] = __floats2bfloat162_rn(v.z, v.w);
    }
}

__global__ void k_gather(const int* __restrict__ seq, const float* __restrict__ emb) {
    int m = blockIdx.x;
    const float4* s = (const float4*)(emb + (size_t)seq[m] * EMB);
    float4 v = s[threadIdx.x];
    __nv_bfloat162* d = (__nv_bfloat162*)(g_x + (size_t)m * EMB);
    d[2*threadIdx.x]   = __floats2bfloat162_rn(v.x, v.y);
    d[2*threadIdx.x+1] = __floats2bfloat162_rn(v.z, v.w);
}

// ---------------- bf16 GEMM: C[M,N] = A[M,K] @ B[N,K]^T + bias ----------------
#define BM 128
#define BN 128
#define BK 32
#define SPAD 8

__device__ __forceinline__ void cp_async16(void* sd, const void* gs, int nbytes) {
    uint32_t s = (uint32_t)__cvta_generic_to_shared(sd);
    asm volatile("cp.async.cg.shared.global [%0], [%1], 16, %2;\n" :: "r"(s), "l"(gs), "r"(nbytes));
}
#define CP_COMMIT() asm volatile("cp.async.commit_group;\n" ::: "memory")
#define CP_WAIT(n)  asm volatile("cp.async.wait_group %0;\n" :: "n"(n) : "memory")

__device__ __forceinline__ void ldmx4(uint32_t* r, const void* p) {
    uint32_t a = (uint32_t)__cvta_generic_to_shared(p);
    asm volatile("ldmatrix.sync.aligned.m8n8.x4.shared.b16 {%0,%1,%2,%3}, [%4];\n"
                 : "=r"(r[0]), "=r"(r[1]), "=r"(r[2]), "=r"(r[3]) : "r"(a));
}
__device__ __forceinline__ void ldmx2(uint32_t* r, const void* p) {
    uint32_t a = (uint32_t)__cvta_generic_to_shared(p);
    asm volatile("ldmatrix.sync.aligned.m8n8.x2.shared.b16 {%0,%1}, [%2];\n"
                 : "=r"(r[0]), "=r"(r[1]) : "r"(a));
}
__device__ __forceinline__ void mma16816(float* c, const uint32_t* a, const uint32_t* b) {
    asm volatile("mma.sync.aligned.m16n8k16.row.col.f32.bf16.bf16.f32 "
                 "{%0,%1,%2,%3}, {%4,%5,%6,%7}, {%8,%9}, {%0,%1,%2,%3};\n"
                 : "+f"(c[0]), "+f"(c[1]), "+f"(c[2]), "+f"(c[3])
                 : "r"(a[0]), "r"(a[1]), "r"(a[2]), "r"(a[3]), "r"(b[0]), "r"(b[1]));
}

__global__ void __launch_bounds__(256) gemm_bf16(
    const __nv_bfloat16* __restrict__ A, const __nv_bfloat16* __restrict__ B,
    const float* __restrict__ bias, float* __restrict__ C, int N, int K)
{
    __shared__ __nv_bfloat16 As[2][BM][BK + SPAD];
    __shared__ __nv_bfloat16 Bs[2][BN][BK + SPAD];
    const int tid = threadIdx.x, warp = tid >> 5, lane = tid & 31;
    const int wm = warp >> 2, wn = warp & 3;
    const int m0 = blockIdx.y * BM, n0 = blockIdx.x * BN;

    float acc[4][4][4];
    #pragma unroll
    for (int i = 0; i < 4; i++)
        #pragma unroll
        for (int j = 0; j < 4; j++)
            #pragma unroll
            for (int q = 0; q < 4; q++) acc[i][j][q] = 0.f;

    const int ld_row = tid >> 1, ld_c = (tid & 1) * 2;

    auto stage_load = [&](int s, int kt) {
        const int kb = kt * BK;
        const __nv_bfloat16* ag = A + (size_t)(m0 + ld_row) * K + kb + ld_c * 8;
        cp_async16(&As[s][ld_row][ld_c * 8], ag, 16);
        cp_async16(&As[s][ld_row][(ld_c + 1) * 8], ag + 8, 16);
        int brow = n0 + ld_row;
        int ok = (brow < N) ? 16 : 0;
        int cr = (brow < N) ? brow : 0;
        const __nv_bfloat16* bg = B + (size_t)cr * K + kb + ld_c * 8;
        cp_async16(&Bs[s][ld_row][ld_c * 8], bg, ok);
        cp_async16(&Bs[s][ld_row][(ld_c + 1) * 8], bg + 8, ok);
    };

    const int NK = K / BK;
    stage_load(0, 0);
    CP_COMMIT();

    for (int kt = 0; kt < NK; kt++) {
        if (kt + 1 < NK) { stage_load((kt + 1) & 1, kt + 1); CP_COMMIT(); CP_WAIT(1); }
        else            { CP_WAIT(0); }
        __syncthreads();
        const int s = kt & 1;
        #pragma unroll
        for (int ks = 0; ks < 2; ks++) {
            uint32_t af[4][4], bf[4][2];
            #pragma unroll
            for (int mt = 0; mt < 4; mt++)
                ldmx4(af[mt], &As[s][wm*64 + mt*16 + (lane & 15)][ks*16 + (lane >> 4) * 8]);
            #pragma unroll
            for (int nt = 0; nt < 4; nt++)
                ldmx2(bf[nt], &Bs[s][wn*32 + nt*8 + (lane & 7)][ks*16 + ((lane >> 3) & 1) * 8]);
            #pragma unroll
            for (int mt = 0; mt < 4; mt++)
                #pragma unroll
                for (int nt = 0; nt < 4; nt++)
                    mma16816(acc[mt][nt], af[mt], bf[nt]);
        }
        __syncthreads();
    }

    #pragma unroll
    for (int mt = 0; mt < 4; mt++) {
        int r0 = m0 + wm*64 + mt*16 + (lane >> 2);
        #pragma unroll
        for (int nt = 0; nt < 4; nt++) {
            int c0 = n0 + wn*32 + nt*8 + (lane & 3) * 2;
            if (c0 < N) {
                float b0 = bias[c0];
                C[(size_t)r0 * N + c0]     = acc[mt][nt][0] + b0;
                C[(size_t)(r0+8) * N + c0] = acc[mt][nt][2] + b0;
            }
            if (c0 + 1 < N) {
                float b1 = bias[c0 + 1];
                C[(size_t)r0 * N + c0+1]     = acc[mt][nt][1] + b1;
                C[(size_t)(r0+8) * N + c0+1] = acc[mt][nt][3] + b1;
            }
        }
    }
}

// ---------------- persistent LSTM ----------------
__device__ __forceinline__ float4 ld_cg_f4(const float4* p) {
    float4 v;
    asm volatile("ld.global.cg.v4.f32 {%0,%1,%2,%3}, [%4];"
                 : "=f"(v.x), "=f"(v.y), "=f"(v.z), "=f"(v.w) : "l"(p) : "memory");
    return v;
}
__device__ __forceinline__ void st_cg_f32(float* p, float v) {
    asm volatile("st.global.cg.f32 [%0], %1;" :: "l"(p), "f"(v) : "memory");
}
__device__ __forceinline__ void st_release_u32(unsigned* p, unsigned v) {
    asm volatile("st.release.gpu.global.u32 [%0], %1;" :: "l"(p), "r"(v) : "memory");
}
__device__ __forceinline__ unsigned ld_acquire_u32(const unsigned* p) {
    unsigned v;
    asm volatile("ld.acquire.gpu.global.u32 %0, [%1];" : "=r"(v) : "l"(p) : "memory");
    return v;
}
#define FMA2(a, b, c) asm("fma.rn.f32x2 %0, %1, %2, %0;" : "+l"(a) : "l"(b), "l"(c))
#define ADD2(a, b)    asm("add.rn.f32x2 %0, %0, %1;"     : "+l"(a) : "l"(b))
__device__ __forceinline__ float tanh_approx(float x) {
    float y;
    asm("tanh.approx.f32 %0, %1;" : "=f"(y) : "f"(x));
    return y;
}

// 128 co-resident CTAs x 256 threads. CTA b owns hidden units [8b,8b+8) ->
// 32 gate rows (i,f,g,o x 8). Thread: r = tid&31 = gate row, seg = warp id =
// 128-wide k-segment. W_hh rows live in registers as packed f32x2 the whole
// kernel. Flag-array grid barrier with release/acquire semantics.
__global__ void __launch_bounds__(256, 1) k_lstm(const float* __restrict__ Whh) {
    const int b = blockIdx.x, tid = threadIdx.x;
    const int r = tid & 31, seg = tid >> 5;
    const int gate = r >> 3, u = r & 7;
    const int row = gate * HID + b * 8 + u;
    const int k0 = seg * 128;

    unsigned long long wq[64];   // 128 scalar weights as 64 x f32x2
    {
        const unsigned long long* wp =
            (const unsigned long long*)(Whh + (size_t)row * HID + k0);
        #pragma unroll
        for (int i = 0; i < 64; i++) wq[i] = wp[i];
    }

    __shared__ float sh_h[HID];
    __shared__ float sm_part[8][32];
    float c_state = 0.f;

    float xg_cur = (seg == 0) ? __ldcg(&g_xgates[row]) : 0.f;

    #pragma unroll 1
    for (int t = 0; t < SEQ; t++) {
        float xg_next = 0.f;
        if (seg == 0 && t + 1 < SEQ)
            xg_next = __ldcg(&g_xgates[(t + 1) * GATES + row]);

        unsigned long long a0 = 0ull, a1 = 0ull, a2 = 0ull, a3 = 0ull;
        if (t > 0) {
            const ulonglong2* hp = (const ulonglong2*)&sh_h[k0];
            #pragma unroll
            for (int i = 0; i < 16; i++) {
                ulonglong2 ha = hp[2 * i];
                ulonglong2 hb = hp[2 * i + 1];
                FMA2(a0, wq[4 * i],     ha.x);
                FMA2(a1, wq[4 * i + 1], ha.y);
                FMA2(a2, wq[4 * i + 2], hb.x);
                FMA2(a3, wq[4 * i + 3], hb.y);
            }
        }
        ADD2(a0, a1); ADD2(a2, a3); ADD2(a0, a2);
        {
            float2 f = *(float2*)&a0;
            sm_part[seg][r] = f.x + f.y;
        }
        __syncthreads();

        if (seg == 0) {
            float g = xg_cur;
            #pragma unroll
            for (int ww = 0; ww < 8; ww++) g += sm_part[ww][r];
            float sg = __fdividef(1.f, 1.f + __expf(-g));
            float tg = tanh_approx(g);
            float v  = (gate == 2) ? tg : sg;
            float iv = __shfl_sync(0xffffffffu, v, u);
            float fv = __shfl_sync(0xffffffffu, v, 8 + u);
            float gv = __shfl_sync(0xffffffffu, v, 16 + u);
            float ov = __shfl_sync(0xffffffffu, v, 24 + u);
            c_state  = fv * c_state + iv * gv;   // meaningful on r<8 only
            float h  = ov * tanh_approx(c_state);
            if (r < 8) {
                st_cg_f32(&g_h[(t + 1) & 1][b * 8 + r], h);
                g_hs[t * HID + b * 8 + r] = __float2bfloat16(h);
            }
            __syncwarp();
            if (tid == 0) st_release_u32(&g_flag[b], (unsigned)(t + 1));
        }
        xg_cur = xg_next;

        if (t < SEQ - 1) {
            if (tid < NCTA) {
                const unsigned tgt = (unsigned)(t + 1);
                while (ld_acquire_u32(&g_flag[tid]) < tgt) {}
            }
            __syncthreads();
            float4 hv = ld_cg_f4((const float4*)&g_h[(t + 1) & 1][tid * 4]);
            *((float4*)&sh_h[tid * 4]) = hv;
            __syncthreads();
        }
    }
}

// ---------------- log_softmax, row cached in dynamic smem ----------------
__global__ void __launch_bounds__(512) k_lsm(float* __restrict__ out) {
    extern __shared__ float srow[];
    float* row = out + (size_t)blockIdx.x * VOC;
    __shared__ float rbuf[16];
    __shared__ float sres;
    const int tid = threadIdx.x, wid = tid >> 5, lane = tid & 31;

    float mx = -1e30f;
    for (int i = tid; i < VOC; i += 512) {
        float v = row[i];
        srow[i] = v;
        mx = fmaxf(mx, v);
    }
    #pragma unroll
    for (int o = 16; o; o >>= 1) mx = fmaxf(mx, __shfl_xor_sync(0xffffffffu, mx, o));
    if (lane == 0) rbuf[wid] = mx;
    __syncthreads();
    if (tid == 0) {
        float m = rbuf[0];
        #pragma unroll
        for (int i = 1; i < 16; i++) m = fmaxf(m, rbuf[i]);
        sres = m;
    }
    __syncthreads();
    mx = sres;
    __syncthreads();

    float s = 0.f;
    for (int i = tid; i < VOC; i += 512) s += __expf(srow[i] - mx);
    #pragma unroll
    for (int o = 16; o; o >>= 1) s += __shfl_xor_sync(0xffffffffu, s, o);
    if (lane == 0) rbuf[wid] = s;
    __syncthreads();
    if (tid == 0) {
        float tt = 0.f;
        #pragma unroll
        for (int i = 0; i < 16; i++) tt += rbuf[i];
        sres = mx + logf(tt);
    }
    __syncthreads();
    float lse = sres;
    for (int i = tid; i < VOC; i += 512) row[i] = srow[i] - lse;
}

// ---------------- launch ----------------
extern "C" void kernel_launch(void* const* d_in, const int* in_sizes, int n_in,
                              void* d_out, int out_size) {
    const int*   seq  = (const int*)  d_in[0];
    const float* emb  = (const float*)d_in[1];
    const float* Wih  = (const float*)d_in[2];
    const float* Whh  = (const float*)d_in[3];
    const float* bih  = (const float*)d_in[4];
    const float* bhh  = (const float*)d_in[5];
    const float* Wout = (const float*)d_in[6];
    const float* bout = (const float*)d_in[7];
    float* out = (float*)d_out;

    void *p_x, *p_wih, *p_wout, *p_hs, *p_xg, *p_b4;
    cudaGetSymbolAddress(&p_x,    g_x);
    cudaGetSymbolAddress(&p_wih,  g_Wih);
    cudaGetSymbolAddress(&p_wout, g_Wout);
    cudaGetSymbolAddress(&p_hs,   g_hs);
    cudaGetSymbolAddress(&p_xg,   g_xgates);
    cudaGetSymbolAddress(&p_b4,   g_bias4);

    // Unconditional (no static guards allowed): host-side attribute set,
    // idempotent, not a stream operation.
    const int lsm_smem = VOC * (int)sizeof(float);
    cudaFuncSetAttribute(k_lsm, cudaFuncAttributeMaxDynamicSharedMemorySize, lsm_smem);

    k_init<<<1, 128>>>();
    k_bias<<<GATES / 256, 256>>>(bih, bhh);

    size_t n4_ih  = (size_t)GATES * EMB / 4;
    size_t n4_out = (size_t)VOC * HID / 4;
    k_conv<<<(unsigned)((n4_ih  + 255) / 256), 256>>>(Wih,  (__nv_bfloat16*)p_wih,  n4_ih);
    k_conv<<<(unsigned)((n4_out + 255) / 256), 256>>>(Wout, (__nv_bfloat16*)p_wout, n4_out);
    k_gather<<<SEQ, 256>>>(seq, emb);

    {   // xgates = x @ W_ih^T + (b_ih + b_hh)
        dim3 grid(GATES / BN, SEQ / BM);
        gemm_bf16<<<grid, 256>>>((const __nv_bfloat16*)p_x, (const __nv_bfloat16*)p_wih,
                                 (const float*)p_b4, (float*)p_xg, GATES, EMB);
    }

    k_lstm<<<NCTA, 256>>>(Whh);

    {   // logits = hs @ W_out^T + b_out -> d_out
        dim3 grid((VOC + BN - 1) / BN, SEQ / BM);
        gemm_bf16<<<grid, 256>>>((const __nv_bfloat16*)p_hs, (const __nv_bfloat16*)p_wout,
                                 bout, out, VOC, HID);
    }

    k_lsm<<<SEQ, 512, lsm_smem>>>(out);
}

// round 7
// speedup vs baseline: 3.1033x; 3.1033x over previous
#include <cuda_runtime.h>
#include <cuda_bf16.h>
#include <cstdint>
#include <cstddef>

#define SEQ   2048
#define EMB   1024
#define HID   1024
#define VOC   50257
#define GATES 4096
#define NCTA  128

// ---------------- device scratch (static) ----------------
__device__ __nv_bfloat16 g_x[SEQ * EMB];
__device__ __nv_bfloat16 g_Wih[GATES * EMB];
__device__ __nv_bfloat16 g_Wout[(size_t)VOC * HID];
__device__ __nv_bfloat16 g_hs[SEQ * HID];
__device__ float         g_xgates[SEQ * GATES];
__device__ float         g_h[2][HID];
__device__ float         g_bias4[GATES];
__device__ unsigned      g_flag[NCTA];

// ---------------- prep kernels (merged to shift ncu capture slot) ----------------
// k_init2: flag reset + bias sum. grid 16x256.
__global__ void k_init2(const float* __restrict__ bih, const float* __restrict__ bhh) {
    int i = blockIdx.x * blockDim.x + threadIdx.x;
    if (i < NCTA) g_flag[i] = 0u;
    if (i < GATES) g_bias4[i] = bih[i] + bhh[i];
}

// k_prep: blocks [0,SEQ) do embedding gather -> g_x (bf16);
//         blocks [SEQ, SEQ + n4_ih/256) convert W_ih fp32 -> bf16.
__global__ void k_prep(const int* __restrict__ seq, const float* __restrict__ emb,
                       const float* __restrict__ Wih) {
    int blk = blockIdx.x;
    if (blk < SEQ) {
        const float4* s = (const float4*)(emb + (size_t)seq[blk] * EMB);
        float4 v = s[threadIdx.x];
        __nv_bfloat162* d = (__nv_bfloat162*)(g_x + (size_t)blk * EMB);
        d[2 * threadIdx.x]     = __floats2bfloat162_rn(v.x, v.y);
        d[2 * threadIdx.x + 1] = __floats2bfloat162_rn(v.z, v.w);
    } else {
        size_t i = (size_t)(blk - SEQ) * blockDim.x + threadIdx.x;  // float4 index
        float4 v = ((const float4*)Wih)[i];
        __nv_bfloat162* d2 = (__nv_bfloat162*)g_Wih;
        d2[2 * i]     = __floats2bfloat162_rn(v.x, v.y);
        d2[2 * i + 1] = __floats2bfloat162_rn(v.z, v.w);
    }
}

__global__ void k_conv(const float* __restrict__ src, __nv_bfloat16* __restrict__ dst, size_t n4) {
    size_t i = (size_t)blockIdx.x * blockDim.x + threadIdx.x;
    if (i < n4) {
        float4 v = ((const float4*)src)[i];
        __nv_bfloat162* d2 = (__nv_bfloat162*)dst;
        d2[2*i]   = __floats2bfloat162_rn(v.x, v.y);
        d2[2*i+1] = __floats2bfloat162_rn(v.z, v.w);
    }
}

// ---------------- bf16 GEMM: C[M,N] = A[M,K] @ B[N,K]^T + bias ----------------
#define BM 128
#define BN 128
#define BK 32
#define SPAD 8

__device__ __forceinline__ void cp_async16(void* sd, const void* gs, int nbytes) {
    uint32_t s = (uint32_t)__cvta_generic_to_shared(sd);
    asm volatile("cp.async.cg.shared.global [%0], [%1], 16, %2;\n" :: "r"(s), "l"(gs), "r"(nbytes));
}
#define CP_COMMIT() asm volatile("cp.async.commit_group;\n" ::: "memory")
#define CP_WAIT(n)  asm volatile("cp.async.wait_group %0;\n" :: "n"(n) : "memory")

__device__ __forceinline__ void ldmx4(uint32_t* r, const void* p) {
    uint32_t a = (uint32_t)__cvta_generic_to_shared(p);
    asm volatile("ldmatrix.sync.aligned.m8n8.x4.shared.b16 {%0,%1,%2,%3}, [%4];\n"
                 : "=r"(r[0]), "=r"(r[1]), "=r"(r[2]), "=r"(r[3]) : "r"(a));
}
__device__ __forceinline__ void ldmx2(uint32_t* r, const void* p) {
    uint32_t a = (uint32_t)__cvta_generic_to_shared(p);
    asm volatile("ldmatrix.sync.aligned.m8n8.x2.shared.b16 {%0,%1}, [%2];\n"
                 : "=r"(r[0]), "=r"(r[1]) : "r"(a));
}
__device__ __forceinline__ void mma16816(float* c, const uint32_t* a, const uint32_t* b) {
    asm volatile("mma.sync.aligned.m16n8k16.row.col.f32.bf16.bf16.f32 "
                 "{%0,%1,%2,%3}, {%4,%5,%6,%7}, {%8,%9}, {%0,%1,%2,%3};\n"
                 : "+f"(c[0]), "+f"(c[1]), "+f"(c[2]), "+f"(c[3])
                 : "r"(a[0]), "r"(a[1]), "r"(a[2]), "r"(a[3]), "r"(b[0]), "r"(b[1]));
}

__global__ void __launch_bounds__(256) gemm_bf16(
    const __nv_bfloat16* __restrict__ A, const __nv_bfloat16* __restrict__ B,
    const float* __restrict__ bias, float* __restrict__ C, int N, int K)
{
    __shared__ __nv_bfloat16 As[2][BM][BK + SPAD];
    __shared__ __nv_bfloat16 Bs[2][BN][BK + SPAD];
    const int tid = threadIdx.x, warp = tid >> 5, lane = tid & 31;
    const int wm = warp >> 2, wn = warp & 3;
    const int m0 = blockIdx.y * BM, n0 = blockIdx.x * BN;

    float acc[4][4][4];
    #pragma unroll
    for (int i = 0; i < 4; i++)
        #pragma unroll
        for (int j = 0; j < 4; j++)
            #pragma unroll
            for (int q = 0; q < 4; q++) acc[i][j][q] = 0.f;

    const int ld_row = tid >> 1, ld_c = (tid & 1) * 2;

    auto stage_load = [&](int s, int kt) {
        const int kb = kt * BK;
        const __nv_bfloat16* ag = A + (size_t)(m0 + ld_row) * K + kb + ld_c * 8;
        cp_async16(&As[s][ld_row][ld_c * 8], ag, 16);
        cp_async16(&As[s][ld_row][(ld_c + 1) * 8], ag + 8, 16);
        int brow = n0 + ld_row;
        int ok = (brow < N) ? 16 : 0;
        int cr = (brow < N) ? brow : 0;
        const __nv_bfloat16* bg = B + (size_t)cr * K + kb + ld_c * 8;
        cp_async16(&Bs[s][ld_row][ld_c * 8], bg, ok);
        cp_async16(&Bs[s][ld_row][(ld_c + 1) * 8], bg + 8, ok);
    };

    const int NK = K / BK;
    stage_load(0, 0);
    CP_COMMIT();

    for (int kt = 0; kt < NK; kt++) {
        if (kt + 1 < NK) { stage_load((kt + 1) & 1, kt + 1); CP_COMMIT(); CP_WAIT(1); }
        else            { CP_WAIT(0); }
        __syncthreads();
        const int s = kt & 1;
        #pragma unroll
        for (int ks = 0; ks < 2; ks++) {
            uint32_t af[4][4], bf[4][2];
            #pragma unroll
            for (int mt = 0; mt < 4; mt++)
                ldmx4(af[mt], &As[s][wm*64 + mt*16 + (lane & 15)][ks*16 + (lane >> 4) * 8]);
            #pragma unroll
            for (int nt = 0; nt < 4; nt++)
                ldmx2(bf[nt], &Bs[s][wn*32 + nt*8 + (lane & 7)][ks*16 + ((lane >> 3) & 1) * 8]);
            #pragma unroll
            for (int mt = 0; mt < 4; mt++)
                #pragma unroll
                for (int nt = 0; nt < 4; nt++)
                    mma16816(acc[mt][nt], af[mt], bf[nt]);
        }
        __syncthreads();
    }

    #pragma unroll
    for (int mt = 0; mt < 4; mt++) {
        int r0 = m0 + wm*64 + mt*16 + (lane >> 2);
        #pragma unroll
        for (int nt = 0; nt < 4; nt++) {
            int c0 = n0 + wn*32 + nt*8 + (lane & 3) * 2;
            if (c0 < N) {
                float b0 = bias[c0];
                C[(size_t)r0 * N + c0]     = acc[mt][nt][0] + b0;
                C[(size_t)(r0+8) * N + c0] = acc[mt][nt][2] + b0;
            }
            if (c0 + 1 < N) {
                float b1 = bias[c0 + 1];
                C[(size_t)r0 * N + c0+1]     = acc[mt][nt][1] + b1;
                C[(size_t)(r0+8) * N + c0+1] = acc[mt][nt][3] + b1;
            }
        }
    }
}

// ---------------- persistent LSTM (round-3 known-good core) ----------------
__device__ __forceinline__ unsigned ld_cg_u32(const unsigned* p) {
    unsigned v;
    asm volatile("ld.global.cg.u32 %0, [%1];" : "=r"(v) : "l"(p) : "memory");
    return v;
}
__device__ __forceinline__ void st_cg_u32(unsigned* p, unsigned v) {
    asm volatile("st.global.cg.u32 [%0], %1;" :: "l"(p), "r"(v) : "memory");
}
__device__ __forceinline__ float4 ld_cg_f4(const float4* p) {
    float4 v;
    asm volatile("ld.global.cg.v4.f32 {%0,%1,%2,%3}, [%4];"
                 : "=f"(v.x), "=f"(v.y), "=f"(v.z), "=f"(v.w) : "l"(p) : "memory");
    return v;
}
__device__ __forceinline__ void st_cg_f32(float* p, float v) {
    asm volatile("st.global.cg.f32 [%0], %1;" :: "l"(p), "f"(v) : "memory");
}
__device__ __forceinline__ float tanh_approx(float x) {
    float y;
    asm("tanh.approx.f32 %0, %1;" : "=f"(y) : "f"(x));
    return y;
}

__global__ void __launch_bounds__(256, 1) k_lstm(const float* __restrict__ Whh) {
    const int b = blockIdx.x, tid = threadIdx.x;
    const int w = tid >> 5, l = tid & 31;
    const int gate = l >> 3, u = l & 7;
    const int row = gate * HID + b * 8 + u;   // gate order i,f,g,o
    const int k0 = w * 128;

    float4 wreg[32];
    {
        const float4* wp = (const float4*)(Whh + (size_t)row * HID + k0);
        #pragma unroll
        for (int i = 0; i < 32; i++) wreg[i] = wp[i];
    }

    __shared__ float sh_h[HID];
    __shared__ float sm_part[8][32];
    float c_state = 0.f;  // valid on warp 0 lanes 0..7

    // xgates prefetched one full step ahead (consumed by warp 0 only)
    float xg_cur = (w == 0) ? __ldcg(&g_xgates[row]) : 0.f;

    #pragma unroll 1
    for (int t = 0; t < SEQ; t++) {
        float xg_next = 0.f;
        if (w == 0 && t + 1 < SEQ)
            xg_next = __ldcg(&g_xgates[(t + 1) * GATES + row]);

        if (t > 0) {
            float4 hv = ld_cg_f4((const float4*)(&g_h[t & 1][tid * 4]));
            *((float4*)&sh_h[tid * 4]) = hv;
        }
        __syncthreads();

        float a0 = 0.f, a1 = 0.f, a2 = 0.f, a3 = 0.f;
        if (t > 0) {
            const float4* hp = (const float4*)&sh_h[k0];
            #pragma unroll
            for (int s = 0; s < 32; s++) {
                float4 h4 = hp[s];
                a0 = fmaf(wreg[s].x, h4.x, a0);
                a1 = fmaf(wreg[s].y, h4.y, a1);
                a2 = fmaf(wreg[s].z, h4.z, a2);
                a3 = fmaf(wreg[s].w, h4.w, a3);
            }
        }
        sm_part[w][l] = (a0 + a1) + (a2 + a3);
        __syncthreads();

        if (w == 0) {
            float g = xg_cur;
            #pragma unroll
            for (int ww = 0; ww < 8; ww++) g += sm_part[ww][l];
            float sg = __fdividef(1.f, 1.f + __expf(-g));
            float v  = (gate == 2) ? tanh_approx(g) : sg;
            float iv = __shfl_sync(0xffffffffu, v, u);
            float fv = __shfl_sync(0xffffffffu, v, 8 + u);
            float gv = __shfl_sync(0xffffffffu, v, 16 + u);
            float ov = __shfl_sync(0xffffffffu, v, 24 + u);
            if (l < 8) {
                c_state = fv * c_state + iv * gv;
                float h = ov * tanh_approx(c_state);
                st_cg_f32(&g_h[(t + 1) & 1][b * 8 + l], h);
                g_hs[t * HID + b * 8 + l] = __float2bfloat16(h);
                __threadfence();
            }
        }
        __syncthreads();
        xg_cur = xg_next;

        if (t < SEQ - 1) {
            if (tid == 0) st_cg_u32(&g_flag[b], (unsigned)(t + 1));
            if (tid < NCTA) {
                unsigned tgt = (unsigned)(t + 1);
                while (ld_cg_u32(&g_flag[tid]) < tgt) {}
                __threadfence();
            }
            __syncthreads();
        }
    }
}

// ---------------- log_softmax (round-3 known-good 3-pass) ----------------
__global__ void __launch_bounds__(256) k_lsm(float* __restrict__ out) {
    float* row = out + (size_t)blockIdx.x * VOC;
    __shared__ float rbuf[8];
    __shared__ float sres;
    const int tid = threadIdx.x, wid = tid >> 5, lane = tid & 31;

    float mx = -1e30f;
    for (int i = tid; i < VOC; i += 256) mx = fmaxf(mx, row[i]);
    #pragma unroll
    for (int o = 16; o; o >>= 1) mx = fmaxf(mx, __shfl_xor_sync(0xffffffffu, mx, o));
    if (lane == 0) rbuf[wid] = mx;
    __syncthreads();
    if (tid == 0) {
        float m = rbuf[0];
        #pragma unroll
        for (int i = 1; i < 8; i++) m = fmaxf(m, rbuf[i]);
        sres = m;
    }
    __syncthreads();
    mx = sres;
    __syncthreads();

    float s = 0.f;
    for (int i = tid; i < VOC; i += 256) s += __expf(row[i] - mx);
    #pragma unroll
    for (int o = 16; o; o >>= 1) s += __shfl_xor_sync(0xffffffffu, s, o);
    if (lane == 0) rbuf[wid] = s;
    __syncthreads();
    if (tid == 0) {
        float t = 0.f;
        #pragma unroll
        for (int i = 0; i < 8; i++) t += rbuf[i];
        sres = mx + logf(t);
    }
    __syncthreads();
    float lse = sres;
    for (int i = tid; i < VOC; i += 256) row[i] = row[i] - lse;
}

// ---------------- launch ----------------
extern "C" void kernel_launch(void* const* d_in, const int* in_sizes, int n_in,
                              void* d_out, int out_size) {
    const int*   seq  = (const int*)  d_in[0];
    const float* emb  = (const float*)d_in[1];
    const float* Wih  = (const float*)d_in[2];
    const float* Whh  = (const float*)d_in[3];
    const float* bih  = (const float*)d_in[4];
    const float* bhh  = (const float*)d_in[5];
    const float* Wout = (const float*)d_in[6];
    const float* bout = (const float*)d_in[7];
    float* out = (float*)d_out;

    void *p_x, *p_wih, *p_wout, *p_hs, *p_xg, *p_b4;
    cudaGetSymbolAddress(&p_x,    g_x);
    cudaGetSymbolAddress(&p_wih,  g_Wih);
    cudaGetSymbolAddress(&p_wout, g_Wout);
    cudaGetSymbolAddress(&p_hs,   g_hs);
    cudaGetSymbolAddress(&p_xg,   g_xgates);
    cudaGetSymbolAddress(&p_b4,   g_bias4);

    const size_t n4_ih  = (size_t)GATES * EMB / 4;
    const size_t n4_out = (size_t)VOC * HID / 4;

    // Launch order chosen so k_lstm sits in the ncu capture slot (4th launch).
    k_init2<<<GATES / 256, 256>>>(bih, bhh);                       // 1
    k_prep<<<(unsigned)(SEQ + n4_ih / 256), 256>>>(seq, emb, Wih); // 2

    {   // 3: xgates = x @ W_ih^T + (b_ih + b_hh)
        dim3 grid(GATES / BN, SEQ / BM);
        gemm_bf16<<<grid, 256>>>((const __nv_bfloat16*)p_x, (const __nv_bfloat16*)p_wih,
                                 (const float*)p_b4, (float*)p_xg, GATES, EMB);
    }

    k_lstm<<<NCTA, 256>>>(Whh);                                    // 4  <- profile here

    k_conv<<<(unsigned)((n4_out + 255) / 256), 256>>>(Wout, (__nv_bfloat16*)p_wout, n4_out); // 5

    {   // 6: logits = hs @ W_out^T + b_out -> d_out
        dim3 grid((VOC + BN - 1) / BN, SEQ / BM);
        gemm_bf16<<<grid, 256>>>((const __nv_bfloat16*)p_hs, (const __nv_bfloat16*)p_wout,
                                 bout, out, VOC, HID);
    }

    k_lsm<<<SEQ, 256>>>(out);                                      // 7
}